// round 2
// baseline (speedup 1.0000x reference)
#include <cuda_runtime.h>

// ---------------------------------------------------------------------------
// Swin W-MSA: B=16, C=384, H=W=64, window 8x8, 12 heads, hd=32
// Pipeline: qkv_gemm -> attention (per window*head) -> proj_gemm (+window rev)
// All fp32 (rel_err budget 1e-3 -> exact-path baseline).
// ---------------------------------------------------------------------------

namespace {
constexpr int C_DIM  = 384;
constexpr int NHEADS = 12;
constexpr int HD     = 32;
constexpr int NWIN   = 1024;        // 16 * 8 * 8
constexpr int NTOK   = 64;          // 8 * 8
constexpr int MTOT   = NWIN * NTOK; // 65536 tokens
constexpr int QKV_N  = 3 * C_DIM;   // 1152
constexpr float SCALE = 0.17677669529663687f; // 1/sqrt(32)
}

// Scratch (allocation-free rule: __device__ globals)
__device__ float g_Q[NWIN * NHEADS * NTOK * HD];
__device__ float g_K[NWIN * NHEADS * NTOK * HD];
__device__ float g_V[NWIN * NHEADS * NTOK * HD];
__device__ float g_AO[MTOT * C_DIM];

// ---------------------------------------------------------------------------
// Kernel 1: QKV projection.  C[m][n] = sum_k xw[m][k]*qkv_w[n][k] + qkv_b[n]
// m = token (window-partitioned gather from x), n in [0,1152).
// 128x128x8 tile, 256 threads, 8x8 per-thread register tile.
// Epilogue scatters to g_Q/g_K/g_V laid out [win][head][tok][d]; q pre-scaled.
// ---------------------------------------------------------------------------
__global__ __launch_bounds__(256, 2)
void qkv_gemm_kernel(const float* __restrict__ x,
                     const float* __restrict__ qw,
                     const float* __restrict__ qb)
{
    __shared__ float As[8][132];
    __shared__ float Bs[8][132];

    const int tid = threadIdx.x;
    const int n0 = blockIdx.x * 128;
    const int m0 = blockIdx.y * 128;

    // A-row gather mapping (window partition): fixed per thread
    const int mloc = tid & 127;
    const int m    = m0 + mloc;
    const int widx = m >> 6, t = m & 63;
    const int bb   = widx >> 6, wi = (widx >> 3) & 7, wj = widx & 7;
    const int h    = wi * 8 + (t >> 3), wc = wj * 8 + (t & 7);
    const int abase = bb * C_DIM * 4096 + h * 64 + wc;

    const int krow = tid >> 7;   // A: k start (0/1)
    const int kb   = tid & 7;    // B: k
    const int nb   = tid >> 3;   // B: n start

    const int ty = tid >> 4;     // m sub-tile
    const int tx = tid & 15;     // n sub-tile

    float acc[8][8];
    #pragma unroll
    for (int i = 0; i < 8; i++)
        #pragma unroll
        for (int j = 0; j < 8; j++) acc[i][j] = 0.f;

    for (int k0 = 0; k0 < C_DIM; k0 += 8) {
        #pragma unroll
        for (int l = 0; l < 4; l++) {
            int kl = krow + l * 2;
            As[kl][mloc] = x[abase + (k0 + kl) * 4096];
        }
        #pragma unroll
        for (int l = 0; l < 4; l++) {
            int nl = nb + l * 32;
            Bs[kb][nl] = qw[(n0 + nl) * C_DIM + k0 + kb];
        }
        __syncthreads();
        #pragma unroll
        for (int kk = 0; kk < 8; kk++) {
            float4 a0 = *(const float4*)&As[kk][ty * 8];
            float4 a1 = *(const float4*)&As[kk][ty * 8 + 4];
            float4 b0 = *(const float4*)&Bs[kk][tx * 8];
            float4 b1 = *(const float4*)&Bs[kk][tx * 8 + 4];
            float ra[8] = {a0.x, a0.y, a0.z, a0.w, a1.x, a1.y, a1.z, a1.w};
            float rb[8] = {b0.x, b0.y, b0.z, b0.w, b1.x, b1.y, b1.z, b1.w};
            #pragma unroll
            for (int i = 0; i < 8; i++)
                #pragma unroll
                for (int j = 0; j < 8; j++)
                    acc[i][j] += ra[i] * rb[j];
        }
        __syncthreads();
    }

    // Epilogue: the whole 128-wide n-block lives inside one part (384 = 3*128)
    const int part = n0 / C_DIM;
    const int rem0 = n0 - part * C_DIM + tx * 8; // col base within part
    const int head = rem0 >> 5;
    const int d0   = rem0 & 31;                  // multiple of 8 -> f4 aligned
    float* dst = (part == 0) ? g_Q : (part == 1) ? g_K : g_V;
    const float sc = (part == 0) ? SCALE : 1.0f;

    float bias[8];
    #pragma unroll
    for (int j = 0; j < 8; j++) bias[j] = qb[n0 + tx * 8 + j];

    #pragma unroll
    for (int i = 0; i < 8; i++) {
        int mm = m0 + ty * 8 + i;
        int wwi = mm >> 6, tt = mm & 63;
        int off = ((wwi * NHEADS + head) * NTOK + tt) * HD + d0;
        float4 v0, v1;
        v0.x = (acc[i][0] + bias[0]) * sc;
        v0.y = (acc[i][1] + bias[1]) * sc;
        v0.z = (acc[i][2] + bias[2]) * sc;
        v0.w = (acc[i][3] + bias[3]) * sc;
        v1.x = (acc[i][4] + bias[4]) * sc;
        v1.y = (acc[i][5] + bias[5]) * sc;
        v1.z = (acc[i][6] + bias[6]) * sc;
        v1.w = (acc[i][7] + bias[7]) * sc;
        *(float4*)&dst[off]     = v0;
        *(float4*)&dst[off + 4] = v1;
    }
}

// ---------------------------------------------------------------------------
// Kernel 2: attention per (window, head). 64 threads; thread r owns row r.
// softmax(QK^T + bias) @ V.  Q pre-scaled in kernel 1.
// ---------------------------------------------------------------------------
__global__ __launch_bounds__(64)
void attn_kernel(const float* __restrict__ rpb, const int* __restrict__ rel)
{
    __shared__ float Ks[NTOK * HD];
    __shared__ float Vs[NTOK * HD];
    __shared__ float S[NTOK][NTOK + 1];

    const int w    = blockIdx.x / NHEADS;
    const int head = blockIdx.x % NHEADS;
    const int tid  = threadIdx.x;

    const int base = (w * NHEADS + head) * NTOK * HD;
    const float* Qp = g_Q + base;
    const float* Kp = g_K + base;
    const float* Vp = g_V + base;

    // cooperative K/V load (512 float4s, coalesced)
    #pragma unroll
    for (int l = 0; l < 8; l++) {
        int i4 = tid + l * 64;
        ((float4*)Ks)[i4] = ((const float4*)Kp)[i4];
        ((float4*)Vs)[i4] = ((const float4*)Vp)[i4];
    }
    float q[HD];
    #pragma unroll
    for (int l = 0; l < 8; l++)
        ((float4*)q)[l] = ((const float4*)(Qp + tid * HD))[l];
    __syncthreads();

    float mx = -1e30f;
    #pragma unroll 4
    for (int j = 0; j < NTOK; j++) {
        float s = rpb[rel[tid * NTOK + j] * NHEADS + head];
        #pragma unroll
        for (int d = 0; d < HD; d++) s += q[d] * Ks[j * HD + d];
        S[tid][j] = s;
        mx = fmaxf(mx, s);
    }
    float sum = 0.f;
    #pragma unroll 8
    for (int j = 0; j < NTOK; j++) {
        float e = __expf(S[tid][j] - mx);
        S[tid][j] = e;
        sum += e;
    }
    const float inv = 1.0f / sum;

    float o[HD];
    #pragma unroll
    for (int d = 0; d < HD; d++) o[d] = 0.f;
    #pragma unroll 4
    for (int j = 0; j < NTOK; j++) {
        float p = S[tid][j] * inv;
        #pragma unroll
        for (int d = 0; d < HD; d++) o[d] += p * Vs[j * HD + d];
    }

    float* dst = g_AO + (w * NTOK + tid) * C_DIM + head * HD;
    #pragma unroll
    for (int l = 0; l < 8; l++)
        ((float4*)dst)[l] = ((float4*)o)[l];
}

// ---------------------------------------------------------------------------
// Kernel 3: output projection + window reverse.
// C[m][n] = sum_k AO[m][k]*proj_w[n][k] + proj_b[n]; scatter to (B,C,H,W)
// Epilogue staged through smem so global stores are token-contiguous.
// ---------------------------------------------------------------------------
__global__ __launch_bounds__(256, 2)
void proj_gemm_kernel(const float* __restrict__ pw,
                      const float* __restrict__ pb,
                      float* __restrict__ out)
{
    __shared__ float As[8][132];
    __shared__ float Bs[8][132];
    __shared__ float St[128][17];

    const int tid = threadIdx.x;
    const int n0 = blockIdx.x * 128;
    const int m0 = blockIdx.y * 128;

    const int ka = tid & 7;
    const int ma = tid >> 3;
    const int ty = tid >> 4;
    const int tx = tid & 15;

    float acc[8][8];
    #pragma unroll
    for (int i = 0; i < 8; i++)
        #pragma unroll
        for (int j = 0; j < 8; j++) acc[i][j] = 0.f;

    for (int k0 = 0; k0 < C_DIM; k0 += 8) {
        #pragma unroll
        for (int l = 0; l < 4; l++) {
            int ml = ma + l * 32;
            As[ka][ml] = g_AO[(m0 + ml) * C_DIM + k0 + ka];
            Bs[ka][ml] = pw[(n0 + ml) * C_DIM + k0 + ka];
        }
        __syncthreads();
        #pragma unroll
        for (int kk = 0; kk < 8; kk++) {
            float4 a0 = *(const float4*)&As[kk][ty * 8];
            float4 a1 = *(const float4*)&As[kk][ty * 8 + 4];
            float4 b0 = *(const float4*)&Bs[kk][tx * 8];
            float4 b1 = *(const float4*)&Bs[kk][tx * 8 + 4];
            float ra[8] = {a0.x, a0.y, a0.z, a0.w, a1.x, a1.y, a1.z, a1.w};
            float rb[8] = {b0.x, b0.y, b0.z, b0.w, b1.x, b1.y, b1.z, b1.w};
            #pragma unroll
            for (int i = 0; i < 8; i++)
                #pragma unroll
                for (int j = 0; j < 8; j++)
                    acc[i][j] += ra[i] * rb[j];
        }
        __syncthreads();
    }

    // window-reverse mapping for this thread's staged-read row
    const int mloc = tid & 127;
    const int m = m0 + mloc;
    const int widx = m >> 6, t = m & 63;
    const int bb = widx >> 6, wi = (widx >> 3) & 7, wj = widx & 7;
    const int h = wi * 8 + (t >> 3), wc = wj * 8 + (t & 7);
    const int obase = bb * C_DIM * 4096 + h * 64 + wc;
    const int nll = tid >> 7;  // 0/1

    #pragma unroll
    for (int cch = 0; cch < 8; cch++) {
        if ((tx >> 1) == cch) {
            int colb = (tx & 1) * 8;
            #pragma unroll
            for (int i = 0; i < 8; i++)
                #pragma unroll
                for (int j = 0; j < 8; j++)
                    St[ty * 8 + i][colb + j] =
                        acc[i][j] + pb[n0 + cch * 16 + colb + j];
        }
        __syncthreads();
        #pragma unroll
        for (int l = 0; l < 8; l++) {
            int nl = nll + l * 2;
            float v = St[mloc][nl];
            int n = n0 + cch * 16 + nl;
            out[obase + n * 4096] = v;
        }
        __syncthreads();
    }
}

// ---------------------------------------------------------------------------
extern "C" void kernel_launch(void* const* d_in, const int* in_sizes, int n_in,
                              void* d_out, int out_size)
{
    const float* x      = (const float*)d_in[0];
    const float* qkv_w  = (const float*)d_in[1];
    const float* qkv_b  = (const float*)d_in[2];
    const float* proj_w = (const float*)d_in[3];
    const float* proj_b = (const float*)d_in[4];
    const float* rpb    = (const float*)d_in[5];
    const int*   rel    = (const int*)d_in[6];
    float* out = (float*)d_out;

    dim3 g1(QKV_N / 128, MTOT / 128);   // (9, 512)
    qkv_gemm_kernel<<<g1, 256>>>(x, qkv_w, qkv_b);

    attn_kernel<<<NWIN * NHEADS, 64>>>(rpb, rel);

    dim3 g3(C_DIM / 128, MTOT / 128);   // (3, 512)
    proj_gemm_kernel<<<g3, 256>>>(proj_w, proj_b, out);
}

// round 6
// speedup vs baseline: 1.5965x; 1.5965x over previous
#include <cuda_runtime.h>
#include <cuda_bf16.h>

// ---------------------------------------------------------------------------
// Swin W-MSA: B=16, C=384, H=W=64, window 8x8, 12 heads, hd=32
// qkv_gemm (split-bf16 tensor core) -> attention (flash, fp32) -> proj_gemm
// ---------------------------------------------------------------------------

namespace {
constexpr int C_DIM  = 384;
constexpr int NHEADS = 12;
constexpr int HD     = 32;
constexpr int NWIN   = 1024;
constexpr int NTOK   = 64;
constexpr int MTOT   = NWIN * NTOK;   // 65536
constexpr int QKV_N  = 3 * C_DIM;     // 1152
constexpr float SCALE = 0.17677669529663687f;
constexpr int SKW = 18;               // smem row stride in u32 (36 bf16)
}

__device__ float g_Q[NWIN * NHEADS * NTOK * HD];
__device__ float g_K[NWIN * NHEADS * NTOK * HD];
__device__ float g_V[NWIN * NHEADS * NTOK * HD];
__device__ float g_AO[MTOT * C_DIM];

// split fp32 pair -> (hi bf16x2, lo bf16x2)
__device__ __forceinline__ void split2(float f0, float f1,
                                       unsigned& hi, unsigned& lo)
{
    __nv_bfloat16 h0 = __float2bfloat16_rn(f0);
    __nv_bfloat16 h1 = __float2bfloat16_rn(f1);
    float r0 = f0 - __bfloat162float(h0);
    float r1 = f1 - __bfloat162float(h1);
    __nv_bfloat16 l0 = __float2bfloat16_rn(r0);
    __nv_bfloat16 l1 = __float2bfloat16_rn(r1);
    __nv_bfloat162 hh; hh.x = h0; hh.y = h1;
    __nv_bfloat162 ll; ll.x = l0; ll.y = l1;
    hi = *reinterpret_cast<unsigned*>(&hh);
    lo = *reinterpret_cast<unsigned*>(&ll);
}

#define MMA_BF16(C, A0,A1,A2,A3, B0,B1)                                        \
    asm volatile(                                                              \
        "mma.sync.aligned.m16n8k16.row.col.f32.bf16.bf16.f32 "                 \
        "{%0,%1,%2,%3}, {%4,%5,%6,%7}, {%8,%9}, {%0,%1,%2,%3};"                \
        : "+f"((C)[0]), "+f"((C)[1]), "+f"((C)[2]), "+f"((C)[3])               \
        : "r"(A0), "r"(A1), "r"(A2), "r"(A3), "r"(B0), "r"(B1))

// ---------------------------------------------------------------------------
// Kernel 1: QKV projection, 128x128x32 tiles, 8 warps (warp tile 32x64),
// 3-way split-bf16 mma. Epilogue scatters to [win][head][tok][d], q scaled.
// ---------------------------------------------------------------------------
__global__ __launch_bounds__(256, 1)
void qkv_gemm_kernel(const float* __restrict__ x,
                     const float* __restrict__ qw,
                     const float* __restrict__ qb)
{
    __shared__ unsigned Ah_s[128 * SKW];
    __shared__ unsigned Al_s[128 * SKW];
    __shared__ unsigned Bh_s[128 * SKW];
    __shared__ unsigned Bl_s[128 * SKW];

    const int tid  = threadIdx.x;
    const int lane = tid & 31;
    const int warp = tid >> 5;
    const int g    = lane >> 2;   // 0..7
    const int t    = lane & 3;    // 0..3
    const int wm   = warp & 3;    // m-warp: offset *32
    const int wn   = warp >> 2;   // n-warp: offset *64

    const int n0 = blockIdx.x * 128;
    const int m0 = blockIdx.y * 128;

    // A gather mapping (window partition)
    const int mloc = tid & 127;
    const int m    = m0 + mloc;
    {
    }
    const int widx = m >> 6, tk = m & 63;
    const int bb   = widx >> 6, wi = (widx >> 3) & 7, wj = widx & 7;
    const int hh   = wi * 8 + (tk >> 3), wc = wj * 8 + (tk & 7);
    const long abase = (long)bb * C_DIM * 4096 + hh * 64 + wc;
    const int chalf = tid >> 7;   // 0/1: which 16 channels this thread stages

    // B staging mapping
    const int brow = tid >> 3;    // 0..31 (+32*l)
    const int bk4  = tid & 7;     // float4 index along k

    float aReg[16];
    float4 bReg[4];

    // prime first tile
    {
        const float* ap = x + abase + (long)(chalf * 16) * 4096;
        #pragma unroll
        for (int l = 0; l < 16; l++) aReg[l] = ap[(long)l * 4096];
        #pragma unroll
        for (int l = 0; l < 4; l++)
            bReg[l] = *(const float4*)(qw + (long)(n0 + brow + l * 32) * C_DIM
                                          + bk4 * 4);
    }

    float acc[2][8][4];
    #pragma unroll
    for (int i = 0; i < 2; i++)
        #pragma unroll
        for (int j = 0; j < 8; j++)
            #pragma unroll
            for (int r = 0; r < 4; r++) acc[i][j][r] = 0.f;

    const int NITER = C_DIM / 32; // 12
    for (int it = 0; it < NITER; it++) {
        __syncthreads();
        // store staged tile (convert to hi/lo bf16)
        #pragma unroll
        for (int l = 0; l < 8; l++) {
            unsigned hi, lo;
            split2(aReg[2 * l], aReg[2 * l + 1], hi, lo);
            int w = mloc * SKW + chalf * 8 + l;
            Ah_s[w] = hi; Al_s[w] = lo;
        }
        #pragma unroll
        for (int l = 0; l < 4; l++) {
            unsigned h0, l0, h1, l1;
            split2(bReg[l].x, bReg[l].y, h0, l0);
            split2(bReg[l].z, bReg[l].w, h1, l1);
            int w = (brow + l * 32) * SKW + bk4 * 2;
            Bh_s[w] = h0; Bh_s[w + 1] = h1;
            Bl_s[w] = l0; Bl_s[w + 1] = l1;
        }
        __syncthreads();

        // prefetch next tile
        if (it + 1 < NITER) {
            int k0 = (it + 1) * 32;
            const float* ap = x + abase + (long)(k0 + chalf * 16) * 4096;
            #pragma unroll
            for (int l = 0; l < 16; l++) aReg[l] = ap[(long)l * 4096];
            #pragma unroll
            for (int l = 0; l < 4; l++)
                bReg[l] = *(const float4*)(qw + (long)(n0 + brow + l * 32) * C_DIM
                                              + k0 + bk4 * 4);
        }

        // compute: 2 k16 halves
        #pragma unroll
        for (int kh = 0; kh < 2; kh++) {
            unsigned ah[2][4], al[2][4];
            #pragma unroll
            for (int mf = 0; mf < 2; mf++) {
                int r0 = (wm * 32 + mf * 16 + g) * SKW + kh * 8 + t;
                int r1 = r0 + 8 * SKW;
                ah[mf][0] = Ah_s[r0];     ah[mf][1] = Ah_s[r1];
                ah[mf][2] = Ah_s[r0 + 4]; ah[mf][3] = Ah_s[r1 + 4];
                al[mf][0] = Al_s[r0];     al[mf][1] = Al_s[r1];
                al[mf][2] = Al_s[r0 + 4]; al[mf][3] = Al_s[r1 + 4];
            }
            unsigned bh[8][2], bl[8][2];
            #pragma unroll
            for (int nf = 0; nf < 8; nf++) {
                int w = (wn * 64 + nf * 8 + g) * SKW + kh * 8 + t;
                bh[nf][0] = Bh_s[w]; bh[nf][1] = Bh_s[w + 4];
                bl[nf][0] = Bl_s[w]; bl[nf][1] = Bl_s[w + 4];
            }
            #pragma unroll
            for (int mf = 0; mf < 2; mf++)
                #pragma unroll
                for (int nf = 0; nf < 8; nf++) {
                    MMA_BF16(acc[mf][nf], ah[mf][0], ah[mf][1], ah[mf][2], ah[mf][3],
                             bh[nf][0], bh[nf][1]);
                    MMA_BF16(acc[mf][nf], ah[mf][0], ah[mf][1], ah[mf][2], ah[mf][3],
                             bl[nf][0], bl[nf][1]);
                    MMA_BF16(acc[mf][nf], al[mf][0], al[mf][1], al[mf][2], al[mf][3],
                             bh[nf][0], bh[nf][1]);
                }
        }
    }

    // epilogue: scatter to Q/K/V
    const int part = (n0 >= 768) ? 2 : (n0 >= 384) ? 1 : 0;
    float* dst = (part == 0) ? g_Q : (part == 1) ? g_K : g_V;
    const float sc = (part == 0) ? SCALE : 1.0f;
    const int colbase = n0 - part * C_DIM + wn * 64;

    #pragma unroll
    for (int mf = 0; mf < 2; mf++) {
        int row = m0 + wm * 32 + mf * 16 + g;
        int win = row >> 6, tok = row & 63;          // row+8 same window
        #pragma unroll
        for (int nf = 0; nf < 8; nf++) {
            int ncol = colbase + nf * 8 + 2 * t;
            int head = ncol >> 5, d = ncol & 31;
            float b0 = __ldg(&qb[n0 + wn * 64 + nf * 8 + 2 * t]);
            float b1 = __ldg(&qb[n0 + wn * 64 + nf * 8 + 2 * t + 1]);
            long off = ((long)(win * NHEADS + head) * NTOK + tok) * HD + d;
            float2 v0, v1;
            v0.x = (acc[mf][nf][0] + b0) * sc;
            v0.y = (acc[mf][nf][1] + b1) * sc;
            v1.x = (acc[mf][nf][2] + b0) * sc;
            v1.y = (acc[mf][nf][3] + b1) * sc;
            *(float2*)&dst[off]            = v0;
            *(float2*)&dst[off + 8L * HD]  = v1;   // row+8 -> tok+8
        }
    }
}

// ---------------------------------------------------------------------------
// Kernel 2: attention, flash-chunked. 128 threads = 2 (win,head) pairs.
// ---------------------------------------------------------------------------
__global__ __launch_bounds__(128)
void attn_kernel(const float* __restrict__ rpb, const int* __restrict__ rel)
{
    __shared__ float Ks[2][NTOK * HD];
    __shared__ float Vs[2][NTOK * HD];

    const int tid  = threadIdx.x;
    const int pair = tid >> 6;
    const int r    = tid & 63;
    const int gh   = blockIdx.x * 2 + pair;
    const int w    = gh / NHEADS;
    const int head = gh % NHEADS;

    const long base = (long)(w * NHEADS + head) * NTOK * HD;
    const float* Qp = g_Q + base;
    const float* Kp = g_K + base;
    const float* Vp = g_V + base;

    #pragma unroll
    for (int l = 0; l < 8; l++) {
        int i4 = r + l * 64;
        ((float4*)Ks[pair])[i4] = ((const float4*)Kp)[i4];
        ((float4*)Vs[pair])[i4] = ((const float4*)Vp)[i4];
    }
    float q[HD];
    #pragma unroll
    for (int l = 0; l < 8; l++)
        ((float4*)q)[l] = ((const float4*)(Qp + r * HD))[l];
    __syncthreads();

    float mx = -1e30f, sum = 0.f;
    float o[HD];
    #pragma unroll
    for (int d = 0; d < HD; d++) o[d] = 0.f;

    #pragma unroll
    for (int c = 0; c < 4; c++) {
        int rl[16];
        #pragma unroll
        for (int jj = 0; jj < 16; jj++)
            rl[jj] = __ldg(&rel[r * NTOK + c * 16 + jj]);
        float s[16], cm = -1e30f;
        #pragma unroll
        for (int jj = 0; jj < 16; jj++) {
            float v = __ldg(&rpb[rl[jj] * NHEADS + head]);
            const float* kr = &Ks[pair][(c * 16 + jj) * HD];
            #pragma unroll
            for (int d = 0; d < HD; d++) v += q[d] * kr[d];
            s[jj] = v;
            cm = fmaxf(cm, v);
        }
        float nm = fmaxf(mx, cm);
        float corr = __expf(mx - nm);
        sum *= corr;
        #pragma unroll
        for (int d = 0; d < HD; d++) o[d] *= corr;
        #pragma unroll
        for (int jj = 0; jj < 16; jj++) {
            float e = __expf(s[jj] - nm);
            sum += e;
            const float* vr = &Vs[pair][(c * 16 + jj) * HD];
            #pragma unroll
            for (int d = 0; d < HD; d++) o[d] += e * vr[d];
        }
        mx = nm;
    }
    const float inv = 1.0f / sum;

    float* dstp = g_AO + (long)(w * NTOK + r) * C_DIM + head * HD;
    #pragma unroll
    for (int l = 0; l < 8; l++) {
        float4 v;
        v.x = o[l * 4 + 0] * inv; v.y = o[l * 4 + 1] * inv;
        v.z = o[l * 4 + 2] * inv; v.w = o[l * 4 + 3] * inv;
        ((float4*)dstp)[l] = v;
    }
}

// ---------------------------------------------------------------------------
// Kernel 3: output projection (split-bf16 mma) + window reverse via smem stage
// ---------------------------------------------------------------------------
__global__ __launch_bounds__(256, 1)
void proj_gemm_kernel(const float* __restrict__ pw,
                      const float* __restrict__ pb,
                      float* __restrict__ out)
{
    __shared__ unsigned Ah_s[128 * SKW];
    __shared__ unsigned Al_s[128 * SKW];
    __shared__ unsigned Bh_s[128 * SKW];
    __shared__ unsigned Bl_s[128 * SKW];
    __shared__ float St[128][17];

    const int tid  = threadIdx.x;
    const int lane = tid & 31;
    const int warp = tid >> 5;
    const int g    = lane >> 2;
    const int t    = lane & 3;
    const int wm   = warp & 3;
    const int wn   = warp >> 2;

    const int n0 = blockIdx.x * 128;
    const int m0 = blockIdx.y * 128;

    const int arow = tid >> 3;   // 0..31 (+32*l)
    const int ak4  = tid & 7;

    float4 aReg[4], bReg[4];
    #pragma unroll
    for (int l = 0; l < 4; l++) {
        aReg[l] = *(const float4*)(g_AO + (long)(m0 + arow + l * 32) * C_DIM
                                       + ak4 * 4);
        bReg[l] = *(const float4*)(pw + (long)(n0 + arow + l * 32) * C_DIM
                                      + ak4 * 4);
    }

    float acc[2][8][4];
    #pragma unroll
    for (int i = 0; i < 2; i++)
        #pragma unroll
        for (int j = 0; j < 8; j++)
            #pragma unroll
            for (int r = 0; r < 4; r++) acc[i][j][r] = 0.f;

    const int NITER = C_DIM / 32;
    for (int it = 0; it < NITER; it++) {
        __syncthreads();
        #pragma unroll
        for (int l = 0; l < 4; l++) {
            unsigned h0, l0, h1, l1;
            int w = (arow + l * 32) * SKW + ak4 * 2;
            split2(aReg[l].x, aReg[l].y, h0, l0);
            split2(aReg[l].z, aReg[l].w, h1, l1);
            Ah_s[w] = h0; Ah_s[w + 1] = h1;
            Al_s[w] = l0; Al_s[w + 1] = l1;
            split2(bReg[l].x, bReg[l].y, h0, l0);
            split2(bReg[l].z, bReg[l].w, h1, l1);
            Bh_s[w] = h0; Bh_s[w + 1] = h1;
            Bl_s[w] = l0; Bl_s[w + 1] = l1;
        }
        __syncthreads();

        if (it + 1 < NITER) {
            int k0 = (it + 1) * 32;
            #pragma unroll
            for (int l = 0; l < 4; l++) {
                aReg[l] = *(const float4*)(g_AO + (long)(m0 + arow + l * 32) * C_DIM
                                               + k0 + ak4 * 4);
                bReg[l] = *(const float4*)(pw + (long)(n0 + arow + l * 32) * C_DIM
                                              + k0 + ak4 * 4);
            }
        }

        #pragma unroll
        for (int kh = 0; kh < 2; kh++) {
            unsigned ah[2][4], al[2][4];
            #pragma unroll
            for (int mf = 0; mf < 2; mf++) {
                int r0 = (wm * 32 + mf * 16 + g) * SKW + kh * 8 + t;
                int r1 = r0 + 8 * SKW;
                ah[mf][0] = Ah_s[r0];     ah[mf][1] = Ah_s[r1];
                ah[mf][2] = Ah_s[r0 + 4]; ah[mf][3] = Ah_s[r1 + 4];
                al[mf][0] = Al_s[r0];     al[mf][1] = Al_s[r1];
                al[mf][2] = Al_s[r0 + 4]; al[mf][3] = Al_s[r1 + 4];
            }
            unsigned bh[8][2], bl[8][2];
            #pragma unroll
            for (int nf = 0; nf < 8; nf++) {
                int w = (wn * 64 + nf * 8 + g) * SKW + kh * 8 + t;
                bh[nf][0] = Bh_s[w]; bh[nf][1] = Bh_s[w + 4];
                bl[nf][0] = Bl_s[w]; bl[nf][1] = Bl_s[w + 4];
            }
            #pragma unroll
            for (int mf = 0; mf < 2; mf++)
                #pragma unroll
                for (int nf = 0; nf < 8; nf++) {
                    MMA_BF16(acc[mf][nf], ah[mf][0], ah[mf][1], ah[mf][2], ah[mf][3],
                             bh[nf][0], bh[nf][1]);
                    MMA_BF16(acc[mf][nf], ah[mf][0], ah[mf][1], ah[mf][2], ah[mf][3],
                             bl[nf][0], bl[nf][1]);
                    MMA_BF16(acc[mf][nf], al[mf][0], al[mf][1], al[mf][2], al[mf][3],
                             bh[nf][0], bh[nf][1]);
                }
        }
    }

    // window-reverse epilogue, staged through St for coalesced stores
    const int mloc = tid & 127;
    const int m = m0 + mloc;
    const int widx = m >> 6, tk = m & 63;
    const int bb = widx >> 6, wi = (widx >> 3) & 7, wj = widx & 7;
    const int hh = wi * 8 + (tk >> 3), wc = wj * 8 + (tk & 7);
    const long obase = (long)bb * C_DIM * 4096 + hh * 64 + wc;
    const int nll = tid >> 7;

    __syncthreads();  // smem tiles no longer needed; St aliasing safe (distinct)
    #pragma unroll
    for (int cch = 0; cch < 8; cch++) {
        if (wn == (cch >> 2)) {
            int nf0 = (cch & 3) * 2;
            #pragma unroll
            for (int nfl = 0; nfl < 2; nfl++) {
                int nf = nf0 + nfl;
                float b0 = __ldg(&pb[n0 + cch * 16 + nfl * 8 + 2 * t]);
                float b1 = __ldg(&pb[n0 + cch * 16 + nfl * 8 + 2 * t + 1]);
                #pragma unroll
                for (int mf = 0; mf < 2; mf++) {
                    int rr = wm * 32 + mf * 16 + g;
                    St[rr][nfl * 8 + 2 * t]         = acc[mf][nf][0] + b0;
                    St[rr][nfl * 8 + 2 * t + 1]     = acc[mf][nf][1] + b1;
                    St[rr + 8][nfl * 8 + 2 * t]     = acc[mf][nf][2] + b0;
                    St[rr + 8][nfl * 8 + 2 * t + 1] = acc[mf][nf][3] + b1;
                }
            }
        }
        __syncthreads();
        #pragma unroll
        for (int l = 0; l < 8; l++) {
            int nl = nll + l * 2;
            out[obase + (long)(n0 + cch * 16 + nl) * 4096] = St[mloc][nl];
        }
        __syncthreads();
    }
}

// ---------------------------------------------------------------------------
extern "C" void kernel_launch(void* const* d_in, const int* in_sizes, int n_in,
                              void* d_out, int out_size)
{
    const float* x      = (const float*)d_in[0];
    const float* qkv_w  = (const float*)d_in[1];
    const float* qkv_b  = (const float*)d_in[2];
    const float* proj_w = (const float*)d_in[3];
    const float* proj_b = (const float*)d_in[4];
    const float* rpb    = (const float*)d_in[5];
    const int*   rel    = (const int*)d_in[6];
    float* out = (float*)d_out;

    dim3 g1(QKV_N / 128, MTOT / 128);   // (9, 512)
    qkv_gemm_kernel<<<g1, 256>>>(x, qkv_w, qkv_b);

    attn_kernel<<<NWIN * NHEADS / 2, 128>>>(rpb, rel);

    dim3 g3(C_DIM / 128, MTOT / 128);   // (3, 512)
    proj_gemm_kernel<<<g3, 256>>>(proj_w, proj_b, out);
}

// round 7
// speedup vs baseline: 1.7567x; 1.1003x over previous
#include <cuda_runtime.h>
#include <cuda_bf16.h>

// ---------------------------------------------------------------------------
// Swin W-MSA: prep(split/transpose) -> qkv bf16-split GEMM (cp.async+ldmatrix)
//             -> attention (fp32 flash, bias table) -> proj GEMM + window rev
// ---------------------------------------------------------------------------

namespace {
constexpr int C_DIM  = 384;
constexpr int NHEADS = 12;
constexpr int HD     = 32;
constexpr int NWIN   = 1024;
constexpr int NTOK   = 64;
constexpr int MTOT   = NWIN * NTOK;   // 65536
constexpr int QKV_N  = 3 * C_DIM;     // 1152
constexpr float SCALE = 0.17677669529663687f;
constexpr int ROWB   = 80;            // smem row stride bytes (40 bf16): (5r)%8 all distinct
constexpr int ARRB   = 128 * ROWB;    // 10240 bytes per tile array
constexpr int STAGEB = 4 * ARRB;      // Ah,Al,Bh,Bl per stage = 40960
constexpr int SMEM_DYN = 2 * STAGEB;  // 81920
}

// Scratch (__device__ globals: allocation-free rule)
__device__ float g_Q[NWIN * NHEADS * NTOK * HD];
__device__ float g_K[NWIN * NHEADS * NTOK * HD];
__device__ float g_V[NWIN * NHEADS * NTOK * HD];
__device__ __nv_bfloat16 g_Xh[MTOT * C_DIM],  g_Xl[MTOT * C_DIM];
__device__ __nv_bfloat16 g_AOh[MTOT * C_DIM], g_AOl[MTOT * C_DIM];
__device__ __nv_bfloat16 g_Wqh[QKV_N * C_DIM], g_Wql[QKV_N * C_DIM];
__device__ __nv_bfloat16 g_Wph[C_DIM * C_DIM], g_Wpl[C_DIM * C_DIM];
__device__ float g_bias[NHEADS * NTOK * NTOK];

__device__ __forceinline__ unsigned smaddr(const void* p) {
    unsigned r;
    asm("{.reg .u64 t; cvta.to.shared.u64 t, %1; cvt.u32.u64 %0, t;}"
        : "=r"(r) : "l"(p));
    return r;
}

__device__ __forceinline__ void split2(float f0, float f1,
                                       unsigned& hi, unsigned& lo)
{
    __nv_bfloat16 h0 = __float2bfloat16_rn(f0);
    __nv_bfloat16 h1 = __float2bfloat16_rn(f1);
    __nv_bfloat16 l0 = __float2bfloat16_rn(f0 - __bfloat162float(h0));
    __nv_bfloat16 l1 = __float2bfloat16_rn(f1 - __bfloat162float(h1));
    __nv_bfloat162 hh; hh.x = h0; hh.y = h1;
    __nv_bfloat162 ll; ll.x = l0; ll.y = l1;
    hi = *reinterpret_cast<unsigned*>(&hh);
    lo = *reinterpret_cast<unsigned*>(&ll);
}

#define MMA_BF16(C, A0,A1,A2,A3, B0,B1)                                        \
    asm volatile(                                                              \
        "mma.sync.aligned.m16n8k16.row.col.f32.bf16.bf16.f32 "                 \
        "{%0,%1,%2,%3}, {%4,%5,%6,%7}, {%8,%9}, {%0,%1,%2,%3};"                \
        : "+f"((C)[0]), "+f"((C)[1]), "+f"((C)[2]), "+f"((C)[3])               \
        : "r"(A0), "r"(A1), "r"(A2), "r"(A3), "r"(B0), "r"(B1))

#define LDSM4(r0,r1,r2,r3,addr)                                                \
    asm volatile("ldmatrix.sync.aligned.m8n8.x4.shared.b16 {%0,%1,%2,%3},[%4];"\
        : "=r"(r0), "=r"(r1), "=r"(r2), "=r"(r3) : "r"(addr))

#define CPA16(dst,src)                                                         \
    asm volatile("cp.async.cg.shared.global [%0],[%1],16;"                     \
        :: "r"(dst), "l"(src))

// ---------------------------------------------------------------------------
// Prep kernels
// ---------------------------------------------------------------------------
__global__ void prep_w_kernel(const float* __restrict__ qw,
                              const float* __restrict__ pw)
{
    int i = blockIdx.x * 256 + threadIdx.x;
    if (i < QKV_N * C_DIM) {
        float f = qw[i];
        __nv_bfloat16 h = __float2bfloat16_rn(f);
        g_Wqh[i] = h;
        g_Wql[i] = __float2bfloat16_rn(f - __bfloat162float(h));
    }
    if (i < C_DIM * C_DIM) {
        float f = pw[i];
        __nv_bfloat16 h = __float2bfloat16_rn(f);
        g_Wph[i] = h;
        g_Wpl[i] = __float2bfloat16_rn(f - __bfloat162float(h));
    }
}

__global__ void prep_bias_kernel(const float* __restrict__ rpb,
                                 const int* __restrict__ rel)
{
    int i = blockIdx.x * 256 + threadIdx.x;    // NHEADS*4096
    int h = i >> 12, ij = i & 4095;
    g_bias[i] = rpb[rel[ij] * NHEADS + h];
}

// window-partition transpose + split: x(B,C,64,64) -> Xh/Xl[tok][c]
__global__ __launch_bounds__(256)
void prep_x_kernel(const float* __restrict__ x)
{
    __shared__ float tile[96][65];
    const int win = blockIdx.x;
    const int bb = win >> 6, wi = (win >> 3) & 7, wj = win & 7;
    const float* xb = x + (long)bb * C_DIM * 4096 + (wi * 8) * 64 + wj * 8;
    const int tid = threadIdx.x;
    const int tok = tid >> 2, qd = tid & 3;

    for (int p = 0; p < 4; p++) {
        const int c0 = p * 96;
        #pragma unroll
        for (int i = 0; i < 24; i++) {
            int idx = i * 256 + tid;
            int c = idx >> 6, tk = idx & 63;
            tile[c][tk] = xb[(long)(c0 + c) * 4096 + (tk >> 3) * 64 + (tk & 7)];
        }
        __syncthreads();
        #pragma unroll
        for (int cc = 0; cc < 3; cc++) {
            int cbase = (qd * 3 + cc) * 8;
            unsigned hp[4], lp[4];
            #pragma unroll
            for (int j = 0; j < 4; j++)
                split2(tile[cbase + 2 * j][tok], tile[cbase + 2 * j + 1][tok],
                       hp[j], lp[j]);
            long e = (long)(win * 64 + tok) * C_DIM + c0 + cbase;
            *(uint4*)&g_Xh[e] = make_uint4(hp[0], hp[1], hp[2], hp[3]);
            *(uint4*)&g_Xl[e] = make_uint4(lp[0], lp[1], lp[2], lp[3]);
        }
        __syncthreads();
    }
}

// ---------------------------------------------------------------------------
// cp.async stage fill: Ah,Al,Bh,Bl 128x32 bf16 tiles (16B chunks, 2/thread/arr)
// ---------------------------------------------------------------------------
__device__ __forceinline__ void issue_tile(unsigned sbase,
    const __nv_bfloat16* pAh, const __nv_bfloat16* pAl,
    const __nv_bfloat16* pBh, const __nv_bfloat16* pBl,
    long aoff, long boff)
{
    CPA16(sbase,                pAh + aoff);
    CPA16(sbase + 16,           pAh + aoff + 8);
    CPA16(sbase + ARRB,         pAl + aoff);
    CPA16(sbase + ARRB + 16,    pAl + aoff + 8);
    CPA16(sbase + 2*ARRB,       pBh + boff);
    CPA16(sbase + 2*ARRB + 16,  pBh + boff + 8);
    CPA16(sbase + 3*ARRB,       pBl + boff);
    CPA16(sbase + 3*ARRB + 16,  pBl + boff + 8);
}

// ---------------------------------------------------------------------------
// Kernel 1: QKV GEMM  (128x128x32 tiles, 8 warps, split-bf16 x3, ldmatrix)
// ---------------------------------------------------------------------------
__global__ __launch_bounds__(256)
void qkv_gemm_v3(const float* __restrict__ qb)
{
    extern __shared__ __align__(16) char dyn[];
    const unsigned sd = smaddr(dyn);

    const int tid = threadIdx.x, lane = tid & 31, warp = tid >> 5;
    const int g = lane >> 2, t = lane & 3;
    const int wm = warp & 3, wn = warp >> 2;
    const int n0 = blockIdx.x * 128, m0 = blockIdx.y * 128;

    // cp.async mapping: thread -> (row, 2 chunks)
    const int crow = tid >> 1, cc = (tid & 1) * 2;
    const unsigned csm = crow * ROWB + cc * 16;
    const long asrc = (long)(m0 + crow) * C_DIM + cc * 8;
    const long bsrc = (long)(n0 + crow) * C_DIM + cc * 8;

    // ldmatrix lane bases
    const unsigned a_base = (wm * 32 + (lane & 15)) * ROWB + (lane >> 4) * 16;
    const unsigned b_base = 2 * ARRB +
        (wn * 64 + ((lane & 7) | ((lane >> 4) << 3))) * ROWB +
        ((lane >> 3) & 1) * 16;

    float acc[2][8][4];
    #pragma unroll
    for (int i = 0; i < 2; i++)
        #pragma unroll
        for (int j = 0; j < 8; j++)
            #pragma unroll
            for (int r = 0; r < 4; r++) acc[i][j][r] = 0.f;

    issue_tile(sd + csm, g_Xh, g_Xl, g_Wqh, g_Wql, asrc, bsrc);
    asm volatile("cp.async.commit_group;");

    const int NIT = C_DIM / 32;  // 12
    for (int it = 0; it < NIT; it++) {
        if (it + 1 < NIT) {
            issue_tile(sd + ((it + 1) & 1) * STAGEB + csm,
                       g_Xh, g_Xl, g_Wqh, g_Wql,
                       asrc + (it + 1) * 32, bsrc + (it + 1) * 32);
            asm volatile("cp.async.commit_group;");
            asm volatile("cp.async.wait_group 1;");
        } else {
            asm volatile("cp.async.wait_group 0;");
        }
        __syncthreads();
        const unsigned sb = sd + (it & 1) * STAGEB;
        #pragma unroll
        for (int kh = 0; kh < 2; kh++) {
            unsigned ah[2][4], al[2][4];
            #pragma unroll
            for (int mf = 0; mf < 2; mf++) {
                unsigned ad = sb + a_base + mf * (16 * ROWB) + kh * 32;
                LDSM4(ah[mf][0], ah[mf][1], ah[mf][2], ah[mf][3], ad);
                LDSM4(al[mf][0], al[mf][1], al[mf][2], al[mf][3], ad + ARRB);
            }
            #pragma unroll
            for (int nfp = 0; nfp < 4; nfp++) {
                unsigned bd = sb + b_base + nfp * (16 * ROWB) + kh * 32;
                unsigned bh0, bh1, bh2, bh3, bl0, bl1, bl2, bl3;
                LDSM4(bh0, bh1, bh2, bh3, bd);
                LDSM4(bl0, bl1, bl2, bl3, bd + ARRB);
                #pragma unroll
                for (int mf = 0; mf < 2; mf++) {
                    MMA_BF16(acc[mf][2*nfp],   ah[mf][0],ah[mf][1],ah[mf][2],ah[mf][3], bh0,bh1);
                    MMA_BF16(acc[mf][2*nfp],   ah[mf][0],ah[mf][1],ah[mf][2],ah[mf][3], bl0,bl1);
                    MMA_BF16(acc[mf][2*nfp],   al[mf][0],al[mf][1],al[mf][2],al[mf][3], bh0,bh1);
                    MMA_BF16(acc[mf][2*nfp+1], ah[mf][0],ah[mf][1],ah[mf][2],ah[mf][3], bh2,bh3);
                    MMA_BF16(acc[mf][2*nfp+1], ah[mf][0],ah[mf][1],ah[mf][2],ah[mf][3], bl2,bl3);
                    MMA_BF16(acc[mf][2*nfp+1], al[mf][0],al[mf][1],al[mf][2],al[mf][3], bh2,bh3);
                }
            }
        }
        __syncthreads();
    }

    // epilogue: scatter to Q/K/V [win][head][tok][d], q pre-scaled
    const int part = (n0 >= 768) ? 2 : (n0 >= 384) ? 1 : 0;
    float* dst = (part == 0) ? g_Q : (part == 1) ? g_K : g_V;
    const float sc = (part == 0) ? SCALE : 1.0f;
    const int colbase = n0 - part * C_DIM + wn * 64;

    #pragma unroll
    for (int mf = 0; mf < 2; mf++) {
        int row = m0 + wm * 32 + mf * 16 + g;
        int win = row >> 6, tok = row & 63;
        #pragma unroll
        for (int nf = 0; nf < 8; nf++) {
            int ncol = colbase + nf * 8 + 2 * t;
            int head = ncol >> 5, d = ncol & 31;
            float b0 = __ldg(&qb[n0 + wn * 64 + nf * 8 + 2 * t]);
            float b1 = __ldg(&qb[n0 + wn * 64 + nf * 8 + 2 * t + 1]);
            long off = ((long)(win * NHEADS + head) * NTOK + tok) * HD + d;
            float2 v0, v1;
            v0.x = (acc[mf][nf][0] + b0) * sc;
            v0.y = (acc[mf][nf][1] + b1) * sc;
            v1.x = (acc[mf][nf][2] + b0) * sc;
            v1.y = (acc[mf][nf][3] + b1) * sc;
            *(float2*)&dst[off]           = v0;
            *(float2*)&dst[off + 8L * HD] = v1;
        }
    }
}

// ---------------------------------------------------------------------------
// Kernel 2: attention (flash-chunked, fp32). Writes split-bf16 AO.
// ---------------------------------------------------------------------------
__global__ __launch_bounds__(128)
void attn_kernel(int dummy)
{
    __shared__ float Ks[2][NTOK * HD];
    __shared__ float Vs[2][NTOK * HD];

    const int tid = threadIdx.x;
    const int pair = tid >> 6, r = tid & 63;
    const int gh = blockIdx.x * 2 + pair;
    const int w = gh / NHEADS, head = gh % NHEADS;

    const long base = (long)(w * NHEADS + head) * NTOK * HD;
    const float* Qp = g_Q + base;
    const float* Kp = g_K + base;
    const float* Vp = g_V + base;

    #pragma unroll
    for (int l = 0; l < 8; l++) {
        int i4 = r + l * 64;
        ((float4*)Ks[pair])[i4] = ((const float4*)Kp)[i4];
        ((float4*)Vs[pair])[i4] = ((const float4*)Vp)[i4];
    }
    float q[HD];
    #pragma unroll
    for (int l = 0; l < 8; l++)
        ((float4*)q)[l] = ((const float4*)(Qp + r * HD))[l];
    __syncthreads();

    const float* bp = g_bias + head * (NTOK * NTOK) + r * NTOK;

    float mx = -1e30f, sum = 0.f;
    float o[HD];
    #pragma unroll
    for (int d = 0; d < HD; d++) o[d] = 0.f;

    #pragma unroll
    for (int c = 0; c < 4; c++) {
        float s[16], cm = -1e30f;
        #pragma unroll
        for (int jj = 0; jj < 16; jj++) {
            float v = __ldg(&bp[c * 16 + jj]);
            const float* kr = &Ks[pair][(c * 16 + jj) * HD];
            #pragma unroll
            for (int d = 0; d < HD; d++) v += q[d] * kr[d];
            s[jj] = v;
            cm = fmaxf(cm, v);
        }
        float nm = fmaxf(mx, cm);
        float corr = __expf(mx - nm);
        sum *= corr;
        #pragma unroll
        for (int d = 0; d < HD; d++) o[d] *= corr;
        #pragma unroll
        for (int jj = 0; jj < 16; jj++) {
            float e = __expf(s[jj] - nm);
            sum += e;
            const float* vr = &Vs[pair][(c * 16 + jj) * HD];
            #pragma unroll
            for (int d = 0; d < HD; d++) o[d] += e * vr[d];
        }
        mx = nm;
    }
    const float inv = 1.0f / sum;

    // split-bf16 output for proj GEMM
    unsigned hp[16], lp[16];
    #pragma unroll
    for (int i = 0; i < 16; i++)
        split2(o[2 * i] * inv, o[2 * i + 1] * inv, hp[i], lp[i]);
    const long mrow = (long)(w * NTOK + r) * C_DIM + head * HD;
    uint4* dh = (uint4*)&g_AOh[mrow];
    uint4* dl = (uint4*)&g_AOl[mrow];
    #pragma unroll
    for (int i = 0; i < 4; i++) {
        dh[i] = make_uint4(hp[4*i], hp[4*i+1], hp[4*i+2], hp[4*i+3]);
        dl[i] = make_uint4(lp[4*i], lp[4*i+1], lp[4*i+2], lp[4*i+3]);
    }
}

// ---------------------------------------------------------------------------
// Kernel 3: proj GEMM + window reverse (smem-staged coalesced scatter)
// ---------------------------------------------------------------------------
__global__ __launch_bounds__(256)
void proj_gemm_v3(const float* __restrict__ pb, float* __restrict__ out)
{
    extern __shared__ __align__(16) char dyn[];
    const unsigned sd = smaddr(dyn);

    const int tid = threadIdx.x, lane = tid & 31, warp = tid >> 5;
    const int g = lane >> 2, t = lane & 3;
    const int wm = warp & 3, wn = warp >> 2;
    const int n0 = blockIdx.x * 128, m0 = blockIdx.y * 128;

    const int crow = tid >> 1, cc = (tid & 1) * 2;
    const unsigned csm = crow * ROWB + cc * 16;
    const long asrc = (long)(m0 + crow) * C_DIM + cc * 8;
    const long bsrc = (long)(n0 + crow) * C_DIM + cc * 8;

    const unsigned a_base = (wm * 32 + (lane & 15)) * ROWB + (lane >> 4) * 16;
    const unsigned b_base = 2 * ARRB +
        (wn * 64 + ((lane & 7) | ((lane >> 4) << 3))) * ROWB +
        ((lane >> 3) & 1) * 16;

    float acc[2][8][4];
    #pragma unroll
    for (int i = 0; i < 2; i++)
        #pragma unroll
        for (int j = 0; j < 8; j++)
            #pragma unroll
            for (int r = 0; r < 4; r++) acc[i][j][r] = 0.f;

    issue_tile(sd + csm, g_AOh, g_AOl, g_Wph, g_Wpl, asrc, bsrc);
    asm volatile("cp.async.commit_group;");

    const int NIT = C_DIM / 32;
    for (int it = 0; it < NIT; it++) {
        if (it + 1 < NIT) {
            issue_tile(sd + ((it + 1) & 1) * STAGEB + csm,
                       g_AOh, g_AOl, g_Wph, g_Wpl,
                       asrc + (it + 1) * 32, bsrc + (it + 1) * 32);
            asm volatile("cp.async.commit_group;");
            asm volatile("cp.async.wait_group 1;");
        } else {
            asm volatile("cp.async.wait_group 0;");
        }
        __syncthreads();
        const unsigned sb = sd + (it & 1) * STAGEB;
        #pragma unroll
        for (int kh = 0; kh < 2; kh++) {
            unsigned ah[2][4], al[2][4];
            #pragma unroll
            for (int mf = 0; mf < 2; mf++) {
                unsigned ad = sb + a_base + mf * (16 * ROWB) + kh * 32;
                LDSM4(ah[mf][0], ah[mf][1], ah[mf][2], ah[mf][3], ad);
                LDSM4(al[mf][0], al[mf][1], al[mf][2], al[mf][3], ad + ARRB);
            }
            #pragma unroll
            for (int nfp = 0; nfp < 4; nfp++) {
                unsigned bd = sb + b_base + nfp * (16 * ROWB) + kh * 32;
                unsigned bh0, bh1, bh2, bh3, bl0, bl1, bl2, bl3;
                LDSM4(bh0, bh1, bh2, bh3, bd);
                LDSM4(bl0, bl1, bl2, bl3, bd + ARRB);
                #pragma unroll
                for (int mf = 0; mf < 2; mf++) {
                    MMA_BF16(acc[mf][2*nfp],   ah[mf][0],ah[mf][1],ah[mf][2],ah[mf][3], bh0,bh1);
                    MMA_BF16(acc[mf][2*nfp],   ah[mf][0],ah[mf][1],ah[mf][2],ah[mf][3], bl0,bl1);
                    MMA_BF16(acc[mf][2*nfp],   al[mf][0],al[mf][1],al[mf][2],al[mf][3], bh0,bh1);
                    MMA_BF16(acc[mf][2*nfp+1], ah[mf][0],ah[mf][1],ah[mf][2],ah[mf][3], bh2,bh3);
                    MMA_BF16(acc[mf][2*nfp+1], ah[mf][0],ah[mf][1],ah[mf][2],ah[mf][3], bl2,bl3);
                    MMA_BF16(acc[mf][2*nfp+1], al[mf][0],al[mf][1],al[mf][2],al[mf][3], bh2,bh3);
                }
            }
        }
        __syncthreads();
    }

    // window-reverse epilogue through smem (reuse dyn as St[128][17])
    float (*St)[17] = reinterpret_cast<float (*)[17]>(dyn);
    const int mloc = tid & 127;
    const int m = m0 + mloc;
    const int widx = m >> 6, tk = m & 63;
    const int bb = widx >> 6, wi = (widx >> 3) & 7, wj = widx & 7;
    const int hh = wi * 8 + (tk >> 3), wc = wj * 8 + (tk & 7);
    const long obase = (long)bb * C_DIM * 4096 + hh * 64 + wc;
    const int nll = tid >> 7;

    __syncthreads();
    #pragma unroll
    for (int cch = 0; cch < 8; cch++) {
        if (wn == (cch >> 2)) {
            int nf0 = (cch & 3) * 2;
            #pragma unroll
            for (int nfl = 0; nfl < 2; nfl++) {
                int nf = nf0 + nfl;
                float b0 = __ldg(&pb[n0 + cch * 16 + nfl * 8 + 2 * t]);
                float b1 = __ldg(&pb[n0 + cch * 16 + nfl * 8 + 2 * t + 1]);
                #pragma unroll
                for (int mf = 0; mf < 2; mf++) {
                    int rr = wm * 32 + mf * 16 + g;
                    St[rr][nfl * 8 + 2 * t]         = acc[mf][nf][0] + b0;
                    St[rr][nfl * 8 + 2 * t + 1]     = acc[mf][nf][1] + b1;
                    St[rr + 8][nfl * 8 + 2 * t]     = acc[mf][nf][2] + b0;
                    St[rr + 8][nfl * 8 + 2 * t + 1] = acc[mf][nf][3] + b1;
                }
            }
        }
        __syncthreads();
        #pragma unroll
        for (int l = 0; l < 8; l++) {
            int nl = nll + l * 2;
            out[obase + (long)(n0 + cch * 16 + nl) * 4096] = St[mloc][nl];
        }
        __syncthreads();
    }
}

// ---------------------------------------------------------------------------
extern "C" void kernel_launch(void* const* d_in, const int* in_sizes, int n_in,
                              void* d_out, int out_size)
{
    const float* x      = (const float*)d_in[0];
    const float* qkv_w  = (const float*)d_in[1];
    const float* qkv_b  = (const float*)d_in[2];
    const float* proj_w = (const float*)d_in[3];
    const float* proj_b = (const float*)d_in[4];
    const float* rpb    = (const float*)d_in[5];
    const int*   rel    = (const int*)d_in[6];
    float* out = (float*)d_out;

    cudaFuncSetAttribute(qkv_gemm_v3,
                         cudaFuncAttributeMaxDynamicSharedMemorySize, SMEM_DYN);
    cudaFuncSetAttribute(proj_gemm_v3,
                         cudaFuncAttributeMaxDynamicSharedMemorySize, SMEM_DYN);

    prep_w_kernel<<<(QKV_N * C_DIM + 255) / 256, 256>>>(qkv_w, proj_w);
    prep_bias_kernel<<<NHEADS * NTOK * NTOK / 256, 256>>>(rpb, rel);
    prep_x_kernel<<<NWIN, 256>>>(x);

    dim3 g1(QKV_N / 128, MTOT / 128);   // (9, 512)
    qkv_gemm_v3<<<g1, 256, SMEM_DYN>>>(qkv_b);

    attn_kernel<<<NWIN * NHEADS / 2, 128>>>(0);

    dim3 g3(C_DIM / 128, MTOT / 128);   // (3, 512)
    proj_gemm_v3<<<g3, 256, SMEM_DYN>>>(proj_b, out);
}